// round 15
// baseline (speedup 1.0000x reference)
#include <cuda_runtime.h>
#include <cuda_fp16.h>
#include <cstddef>

#define D       128
#define H       8
#define HD      16
#define NMAX    50000
#define NPAD    50176          // 392 * 128
#define EMAX    800000
#define LAYERS  3

// ---------------------------------------------------------------------------
// Float scratch: x (residual/pool), colsum partials
// ---------------------------------------------------------------------------
#define OFF_X    ((size_t)0)
#define OFF_PART (OFF_X + (size_t)NMAX * D)
#define NPARTBLK 256
#define SCRATCH_FLOATS (OFF_PART + (size_t)NPARTBLK * D)
__device__ float g_scratch[SCRATCH_FLOATS];

// Packed fp16 activations (single plane, half2 per uint, pairs along K)
#define XPL   ((size_t)NPAD * 64)
#define MIDPL ((size_t)NPAD * 128)
__device__ unsigned g_xp[XPL];
__device__ unsigned g_yp[XPL];
__device__ unsigned g_qp[XPL];
__device__ unsigned g_kp[XPL];
__device__ unsigned g_vp[XPL];
__device__ unsigned g_wvp[XPL];
__device__ unsigned g_midp[MIDPL];

// Int scratch: cnt[N], rowptr[N+1], csr_src[E]
#define IOFF_CNT   0
#define IOFF_ROW   (IOFF_CNT + NMAX)
#define IOFF_SRC   (IOFF_ROW + NMAX + 1)
__device__ int g_iscratch[IOFF_SRC + EMAX];

// Packed fp16 weights, N-MAJOR rows of K-pairs: w[n][kp] (half2 per uint).
#define PQ      (64 * 128)     // DxD matrix (uints)
#define PF      (64 * 256)     // 128x256 / 256x128 (uints)
#define SQ      (LAYERS * PQ)
#define SF      (LAYERS * PF)
#define WQ_OFF  0
#define WK_OFF  (WQ_OFF + SQ)
#define WV_OFF  (WK_OFF + SQ)
#define WO_OFF  (WV_OFF + SQ)
#define WF1_OFF (WO_OFF + SQ)
#define WF2_OFF (WF1_OFF + SF)
#define WPACK_TOTAL (WF2_OFF + SF)
__device__ unsigned g_wpack[WPACK_TOTAL];

// ---------------------------------------------------------------------------
__device__ __forceinline__ unsigned pack2_f16(float a, float b) {
    __half2 h2 = __floats2half2_rn(a, b);
    return *(unsigned*)&h2;
}
__device__ __forceinline__ float2 unpack2_f16(unsigned u) {
    return __half22float2(*(__half2*)&u);
}
__device__ __forceinline__ void cp16(unsigned* smem, const unsigned* gmem) {
    unsigned sa = (unsigned)__cvta_generic_to_shared(smem);
    asm volatile("cp.async.cg.shared.global [%0], [%1], 16;" :: "r"(sa), "l"(gmem));
}
#define LDSM_X4(r0, r1, r2, r3, addr) \
    asm volatile("ldmatrix.sync.aligned.m8n8.x4.shared.b16 {%0,%1,%2,%3}, [%4];" \
                 : "=r"(r0), "=r"(r1), "=r"(r2), "=r"(r3) : "r"(addr))

// ---------------------------------------------------------------------------
__global__ void zero_int(int* __restrict__ p, int n) {
    int i = blockIdx.x * blockDim.x + threadIdx.x;
    int stride = gridDim.x * blockDim.x;
    for (; i < n; i += stride) p[i] = 0;
}

// Embedding gather: float x + packed xp
__global__ void emb_gather(const int* __restrict__ idx, const float* __restrict__ emb,
                           float* __restrict__ x, unsigned* __restrict__ xp, int N) {
    int i = blockIdx.x * blockDim.x + threadIdx.x;
    if (i >= N * 64) return;
    int n = i >> 6;
    int kp = i & 63;
    float2 e = *(const float2*)(emb + (size_t)idx[n] * D + 2 * kp);
    *(float2*)(x + (size_t)n * D + 2 * kp) = e;
    xp[(size_t)n * 64 + kp] = pack2_f16(e.x, e.y);
}

// Combined weight conversion: all 6 weight stacks in ONE launch.
// float [L, K, Nout] -> n-major packed: dst[l*P + n*(K/2) + kp]
__global__ void conv_all(const float* __restrict__ Wq, const float* __restrict__ Wk,
                         const float* __restrict__ Wv, const float* __restrict__ Wo,
                         const float* __restrict__ Wf1, const float* __restrict__ Wf2,
                         unsigned* __restrict__ wp) {
    int idx = blockIdx.x * blockDim.x + threadIdx.x;
    if (idx >= (int)WPACK_TOTAL) return;

    const float* src;
    int K, Nout, rem, dstoff;
    if (idx < 4 * SQ) {
        int which = idx / SQ;
        rem = idx - which * SQ;
        src = (which == 0) ? Wq : (which == 1) ? Wk : (which == 2) ? Wv : Wo;
        K = 128; Nout = 128;
        dstoff = which * SQ;
    } else if (idx < 4 * SQ + SF) {
        rem = idx - 4 * SQ;
        src = Wf1; K = 128; Nout = 256; dstoff = WF1_OFF;
    } else {
        rem = idx - 4 * SQ - SF;
        src = Wf2; K = 256; Nout = 128; dstoff = WF2_OFF;
    }
    int KH = K >> 1;
    int P = KH * Nout;
    int l = rem / P;
    int p = rem - l * P;
    int n = p / KH;
    int kp = p - n * KH;
    float a = src[(size_t)l * K * Nout + (size_t)(2 * kp) * Nout + n];
    float b = src[(size_t)l * K * Nout + (size_t)(2 * kp + 1) * Nout + n];
    wp[dstoff + (size_t)l * P + p] = pack2_f16(a, b);
}

// ---------------------------------------------------------------------------
// CSR build
// ---------------------------------------------------------------------------
__global__ void hist_dst(const int* __restrict__ ei, int E, int* __restrict__ cnt) {
    int j = blockIdx.x * blockDim.x + threadIdx.x;
    if (j < E) atomicAdd(&cnt[ei[E + j]], 1);
}
// Scan + re-zero cnt (cnt reused as 'cur' by csr_scatter, so no extra zero pass).
__global__ void scan_rowptr(int* __restrict__ cnt, int* __restrict__ rowptr, int N) {
    __shared__ int ssum[1024];
    int tid = threadIdx.x;
    int chunk = (N + 1023) / 1024;
    int start = tid * chunk;
    int end = min(start + chunk, N);
    int s = 0;
    for (int i = start; i < end; i++) s += cnt[i];
    ssum[tid] = s;
    __syncthreads();
    int mysum = s;
    for (int o = 1; o < 1024; o <<= 1) {
        int t = (tid >= o) ? ssum[tid - o] : 0;
        __syncthreads();
        ssum[tid] += t;
        __syncthreads();
    }
    int off = ssum[tid] - mysum;
    for (int i = start; i < end; i++) {
        rowptr[i] = off;
        off += cnt[i];
        cnt[i] = 0;
    }
    if (end == N) rowptr[N] = off;
}
__global__ void csr_scatter(const int* __restrict__ ei, int E,
                            const int* __restrict__ rowptr, int* __restrict__ cur,
                            int* __restrict__ csr_src) {
    int j = blockIdx.x * blockDim.x + threadIdx.x;
    if (j >= E) return;
    int d = ei[E + j];
    int pos = atomicAdd(&cur[d], 1);
    csr_src[rowptr[d] + pos] = ei[j];
}

// ---------------------------------------------------------------------------
// fp16 tensor-core GEMM core with ldmatrix fragment loads.
// Block tile 64x128, chunk K=32, 128 threads (4 warps: 2 M x 2 N, 32x64/warp).
// Small tile -> 5 blocks/SM -> ~1.06 waves at N=50000 (vs 1.32 @ 128-row tile).
// ---------------------------------------------------------------------------
#define ASTR 20
#define SM_A 0
#define SM_B 1280
#define STG_UINTS 3840
#define GEMM_DYN_SMEM (2 * STG_UINTS * 4)

__device__ __forceinline__ void mma_f16(float c[4], const unsigned a[4],
                                        unsigned b0, unsigned b1) {
    asm volatile(
        "mma.sync.aligned.m16n8k16.row.col.f32.f16.f16.f32 "
        "{%0,%1,%2,%3}, {%4,%5,%6,%7}, {%8,%9}, {%0,%1,%2,%3};"
        : "+f"(c[0]), "+f"(c[1]), "+f"(c[2]), "+f"(c[3])
        : "r"(a[0]), "r"(a[1]), "r"(a[2]), "r"(a[3]), "r"(b0), "r"(b1));
}

__device__ __forceinline__ void load_stage(
    const unsigned* __restrict__ Ap, int ldA,
    const unsigned* __restrict__ Wp, int ldW,
    int bm, int bn, int chunk, unsigned* s, int tid)
{
    int kp0 = chunk * 16;
    // A: 64 rows x 4 uint4 = 256 -> 2 iters of 128 threads
#pragma unroll
    for (int it = 0; it < 2; it++) {
        int idx = tid + it * 128;
        int r = idx >> 2;
        int c4 = idx & 3;
        cp16(s + SM_A + r * ASTR + c4 * 4,
             Ap + (size_t)(bm + r) * ldA + kp0 + c4 * 4);
    }
    // B: 128 rows x 4 uint4 = 512 -> 4 iters
#pragma unroll
    for (int it = 0; it < 4; it++) {
        int idx = tid + it * 128;
        int r = idx >> 2;
        int c4 = idx & 3;
        cp16(s + SM_B + r * ASTR + c4 * 4,
             Wp + (size_t)(bn + r) * ldW + kp0 + c4 * 4);
    }
    asm volatile("cp.async.commit_group;");
}

__device__ __forceinline__ void gemm_core_p(
    const unsigned* __restrict__ Ap, int ldA,
    const unsigned* __restrict__ Wp, int ldW,
    int K, int bm, int bn,
    unsigned* sm, float acc[2][8][4])
{
    const int tid = threadIdx.x;
    const int lane = tid & 31;
    const int wid = tid >> 5;
    const int warp_m = wid & 1;     // 2 warps along M (32 rows each)
    const int warp_n = wid >> 1;    // 2 warps along N (64 cols each)
    const int sub = lane >> 3;
    const int rin = lane & 7;

    const unsigned sbase = (unsigned)__cvta_generic_to_shared(sm);
    const int a_row = warp_m * 32 + (sub & 1) * 8 + rin;
    const int a_col = (sub >> 1) * 4;
    const int b_row0 = warp_n * 64 + (sub >> 1) * 8 + rin;
    const int b_col = (sub & 1) * 4;

#pragma unroll
    for (int mi = 0; mi < 2; mi++)
#pragma unroll
        for (int ni = 0; ni < 8; ni++)
#pragma unroll
            for (int t = 0; t < 4; t++) acc[mi][ni][t] = 0.0f;

    const int C = K >> 5;
    load_stage(Ap, ldA, Wp, ldW, bm, bn, 0, sm, tid);

    for (int c = 0; c < C; c++) {
        if (c + 1 < C) {
            load_stage(Ap, ldA, Wp, ldW, bm, bn, c + 1,
                       sm + ((c + 1) & 1) * STG_UINTS, tid);
            asm volatile("cp.async.wait_group 1;");
        } else {
            asm volatile("cp.async.wait_group 0;");
        }
        __syncthreads();

        const unsigned stg = sbase + (unsigned)((c & 1) * STG_UINTS) * 4u;

#pragma unroll
        for (int st = 0; st < 2; st++) {
            unsigned ah[2][4];
#pragma unroll
            for (int mi = 0; mi < 2; mi++) {
                unsigned aaddr = stg + ((unsigned)(SM_A + (a_row + mi * 16) * ASTR
                                                   + 8 * st + a_col) << 2);
                LDSM_X4(ah[mi][0], ah[mi][1], ah[mi][2], ah[mi][3], aaddr);
            }
#pragma unroll
            for (int t = 0; t < 4; t++) {
                unsigned b0, b1, b2, b3;
                unsigned baddr = stg + ((unsigned)(SM_B + (b_row0 + t * 16) * ASTR
                                                   + 8 * st + b_col) << 2);
                LDSM_X4(b0, b1, b2, b3, baddr);
#pragma unroll
                for (int mi = 0; mi < 2; mi++) {
                    mma_f16(acc[mi][2 * t + 0], ah[mi], b0, b1);
                    mma_f16(acc[mi][2 * t + 1], ah[mi], b2, b3);
                }
            }
        }
        __syncthreads();
    }
}

// QKV fused: grid.z selects weight/bias/output; packed half2 q/k/v outputs.
__global__ __launch_bounds__(128, 5)
void gemm_qkv(const unsigned* __restrict__ Ap,
              const unsigned* __restrict__ Wpq, const unsigned* __restrict__ Wpk,
              const unsigned* __restrict__ Wpv,
              const float* __restrict__ bq, const float* __restrict__ bk,
              const float* __restrict__ bv,
              unsigned* __restrict__ Cq, unsigned* __restrict__ Ck,
              unsigned* __restrict__ Cv,
              int rows) {
    extern __shared__ unsigned sm[];
    const int z = blockIdx.z;
    const unsigned* Wp = (z == 0) ? Wpq : (z == 1) ? Wpk : Wpv;
    const float* bias  = (z == 0) ? bq  : (z == 1) ? bk  : bv;
    unsigned* C        = (z == 0) ? Cq  : (z == 1) ? Ck  : Cv;
    const int bm = blockIdx.x * 64;
    float acc[2][8][4];
    gemm_core_p(Ap, 64, Wp, 64, 128, bm, 0, sm, acc);

    const int lane = threadIdx.x & 31;
    const int wid = threadIdx.x >> 5;
    const int warp_m = wid & 1, warp_n = wid >> 1;
    const int lr = lane >> 2, lc = lane & 3;
#pragma unroll
    for (int mi = 0; mi < 2; mi++) {
        int row0 = bm + warp_m * 32 + mi * 16 + lr;
        int row1 = row0 + 8;
#pragma unroll
        for (int ni = 0; ni < 8; ni++) {
            int col = warp_n * 64 + ni * 8 + 2 * lc;
            int colp = col >> 1;
            float bs0 = bias[col], bs1 = bias[col + 1];
            if (row0 < rows)
                C[(size_t)row0 * 64 + colp] =
                    pack2_f16(acc[mi][ni][0] + bs0, acc[mi][ni][1] + bs1);
            if (row1 < rows)
                C[(size_t)row1 * 64 + colp] =
                    pack2_f16(acc[mi][ni][2] + bs0, acc[mi][ni][3] + bs1);
        }
    }
}

// GEMM + fused residual/LayerNorm (Nout = 128 = full row per block).
// fp32 residual xio (load-bearing for accuracy), optional packed outputs.
__global__ __launch_bounds__(128, 5)
void gemm_ln(const unsigned* __restrict__ Ap, int ldA,
             const unsigned* __restrict__ Wp, int ldW,
             const float* __restrict__ bias,
             unsigned* __restrict__ yp,
             float* __restrict__ xio,
             unsigned* __restrict__ xpo,
             const float* __restrict__ g, const float* __restrict__ b,
             int rows, int K) {
    extern __shared__ unsigned sm[];
    const int bm = blockIdx.x * 64;
    float acc[2][8][4];
    gemm_core_p(Ap, ldA, Wp, ldW, K, bm, 0, sm, acc);

    const int lane = threadIdx.x & 31;
    const int wid = threadIdx.x >> 5;
    const int warp_m = wid & 1, warp_n = wid >> 1;
    const int lr = lane >> 2, lc = lane & 3;

    float* sred = (float*)sm;   // 64 rows x 2 halves x {sum,sq} = 256 floats

#pragma unroll
    for (int mi = 0; mi < 2; mi++) {
#pragma unroll
        for (int rp = 0; rp < 2; rp++) {
            int r_loc = warp_m * 32 + mi * 16 + lr + 8 * rp;
            int row = bm + r_loc;
            float sum = 0.f, sq = 0.f;
#pragma unroll
            for (int ni = 0; ni < 8; ni++) {
                int col = warp_n * 64 + ni * 8 + 2 * lc;
                float o0 = acc[mi][ni][2 * rp + 0] + bias[col];
                float o1 = acc[mi][ni][2 * rp + 1] + bias[col + 1];
                float x0 = 0.f, x1 = 0.f;
                if (row < rows) {
                    float2 xr = *(const float2*)(xio + (size_t)row * D + col);
                    x0 = xr.x; x1 = xr.y;
                    if (yp)
                        yp[(size_t)row * 64 + (col >> 1)] = pack2_f16(o0, o1);
                }
                float v0 = o0 + x0, v1 = o1 + x1;
                acc[mi][ni][2 * rp + 0] = v0;
                acc[mi][ni][2 * rp + 1] = v1;
                sum += v0 + v1;
                sq += v0 * v0 + v1 * v1;
            }
            sum += __shfl_xor_sync(0xffffffffu, sum, 1);
            sq  += __shfl_xor_sync(0xffffffffu, sq, 1);
            sum += __shfl_xor_sync(0xffffffffu, sum, 2);
            sq  += __shfl_xor_sync(0xffffffffu, sq, 2);
            if (lc == 0) {
                sred[r_loc * 4 + warp_n * 2 + 0] = sum;
                sred[r_loc * 4 + warp_n * 2 + 1] = sq;
            }
        }
    }
    __syncthreads();

#pragma unroll
    for (int mi = 0; mi < 2; mi++) {
#pragma unroll
        for (int rp = 0; rp < 2; rp++) {
            int r_loc = warp_m * 32 + mi * 16 + lr + 8 * rp;
            int row = bm + r_loc;
            if (row >= rows) continue;
            float sum = sred[r_loc * 4 + 0] + sred[r_loc * 4 + 2];
            float sq  = sred[r_loc * 4 + 1] + sred[r_loc * 4 + 3];
            float mean = sum * (1.0f / 128.0f);
            float var = sq * (1.0f / 128.0f) - mean * mean;
            float rstd = rsqrtf(var + 1e-5f);
#pragma unroll
            for (int ni = 0; ni < 8; ni++) {
                int col = warp_n * 64 + ni * 8 + 2 * lc;
                float v0 = acc[mi][ni][2 * rp + 0];
                float v1 = acc[mi][ni][2 * rp + 1];
                float out0 = (v0 - mean) * rstd * g[col] + b[col];
                float out1 = (v1 - mean) * rstd * g[col + 1] + b[col + 1];
                *(float2*)(xio + (size_t)row * D + col) = make_float2(out0, out1);
                if (xpo)
                    xpo[(size_t)row * 64 + (col >> 1)] = pack2_f16(out0, out1);
            }
        }
    }
}

// FFN first GEMM: relu, packed output (Nout = 256 via grid.y)
__global__ __launch_bounds__(128, 5)
void gemm_f1(const unsigned* __restrict__ Ap,
             const unsigned* __restrict__ Wp,
             const float* __restrict__ bias,
             unsigned* __restrict__ outp,
             int rows) {
    extern __shared__ unsigned sm[];
    const int bm = blockIdx.x * 64;
    const int bn = blockIdx.y * 128;
    float acc[2][8][4];
    gemm_core_p(Ap, 64, Wp, 64, 128, bm, bn, sm, acc);

    const int lane = threadIdx.x & 31;
    const int wid = threadIdx.x >> 5;
    const int warp_m = wid & 1, warp_n = wid >> 1;
    const int lr = lane >> 2, lc = lane & 3;
#pragma unroll
    for (int mi = 0; mi < 2; mi++) {
        int row0 = bm + warp_m * 32 + mi * 16 + lr;
        int row1 = row0 + 8;
#pragma unroll
        for (int ni = 0; ni < 8; ni++) {
            int col = bn + warp_n * 64 + ni * 8 + 2 * lc;
            int colp = col >> 1;
            float bs0 = bias[col], bs1 = bias[col + 1];
            float o0 = fmaxf(acc[mi][ni][0] + bs0, 0.f);
            float o1 = fmaxf(acc[mi][ni][1] + bs1, 0.f);
            float o2 = fmaxf(acc[mi][ni][2] + bs0, 0.f);
            float o3 = fmaxf(acc[mi][ni][3] + bs1, 0.f);
            if (row0 < rows)
                outp[(size_t)row0 * 128 + colp] = pack2_f16(o0, o1);
            if (row1 < rows)
                outp[(size_t)row1 * 128 + colp] = pack2_f16(o2, o3);
        }
    }
}

// ---------------------------------------------------------------------------
// CSR attention: warp per destination node, fp16 q/k/v, 2-edge unrolled.
// ---------------------------------------------------------------------------
__global__ void attn_csr(const int* __restrict__ rowptr, const int* __restrict__ csr_src,
                         const unsigned* __restrict__ qh, const unsigned* __restrict__ kh,
                         const unsigned* __restrict__ vh, unsigned* __restrict__ wvp, int N) {
    int warp = blockIdx.x * (blockDim.x >> 5) + (threadIdx.x >> 5);
    if (warp >= N) return;
    int lane = threadIdx.x & 31;
    int colp = lane * 2;

    uint2 qp = *(const uint2*)(qh + (size_t)warp * 64 + colp);
    float2 q01 = unpack2_f16(qp.x);
    float2 q23 = unpack2_f16(qp.y);

    float4 acc = make_float4(0.f, 0.f, 0.f, 0.f);
    float Zh = 0.0f;

    int jb = rowptr[warp];
    int je = rowptr[warp + 1];
    int j = jb;

    for (; j + 1 < je; j += 2) {
        int s0 = csr_src[j];
        int s1 = csr_src[j + 1];
        uint2 ka = *(const uint2*)(kh + (size_t)s0 * 64 + colp);
        uint2 kb = *(const uint2*)(kh + (size_t)s1 * 64 + colp);
        uint2 va = *(const uint2*)(vh + (size_t)s0 * 64 + colp);
        uint2 vb = *(const uint2*)(vh + (size_t)s1 * 64 + colp);

        float2 ka01 = unpack2_f16(ka.x), ka23 = unpack2_f16(ka.y);
        float2 kb01 = unpack2_f16(kb.x), kb23 = unpack2_f16(kb.y);
        float sa = ka01.x * q01.x + ka01.y * q01.y + ka23.x * q23.x + ka23.y * q23.y;
        float sb = kb01.x * q01.x + kb01.y * q01.y + kb23.x * q23.x + kb23.y * q23.y;
        sa += __shfl_xor_sync(0xffffffffu, sa, 1);
        sb += __shfl_xor_sync(0xffffffffu, sb, 1);
        sa += __shfl_xor_sync(0xffffffffu, sa, 2);
        sb += __shfl_xor_sync(0xffffffffu, sb, 2);
        sa = expf(fminf(fmaxf(sa * 0.25f, -5.0f), 5.0f));
        sb = expf(fminf(fmaxf(sb * 0.25f, -5.0f), 5.0f));

        float2 va01 = unpack2_f16(va.x), va23 = unpack2_f16(va.y);
        float2 vb01 = unpack2_f16(vb.x), vb23 = unpack2_f16(vb.y);
        acc.x = fmaf(va01.x, sa, fmaf(vb01.x, sb, acc.x));
        acc.y = fmaf(va01.y, sa, fmaf(vb01.y, sb, acc.y));
        acc.z = fmaf(va23.x, sa, fmaf(vb23.x, sb, acc.z));
        acc.w = fmaf(va23.y, sa, fmaf(vb23.y, sb, acc.w));
        Zh += sa + sb;
    }
    if (j < je) {
        int s0 = csr_src[j];
        uint2 ka = *(const uint2*)(kh + (size_t)s0 * 64 + colp);
        uint2 va = *(const uint2*)(vh + (size_t)s0 * 64 + colp);
        float2 k01 = unpack2_f16(ka.x), k23 = unpack2_f16(ka.y);
        float s = k01.x * q01.x + k01.y * q01.y + k23.x * q23.x + k23.y * q23.y;
        s += __shfl_xor_sync(0xffffffffu, s, 1);
        s += __shfl_xor_sync(0xffffffffu, s, 2);
        s = expf(fminf(fmaxf(s * 0.25f, -5.0f), 5.0f));
        float2 v01 = unpack2_f16(va.x), v23 = unpack2_f16(va.y);
        acc.x = fmaf(v01.x, s, acc.x);
        acc.y = fmaf(v01.y, s, acc.y);
        acc.z = fmaf(v23.x, s, acc.z);
        acc.w = fmaf(v23.y, s, acc.w);
        Zh += s;
    }
    float inv = 1.0f / (Zh + 1e-6f);
    acc.x *= inv; acc.y *= inv; acc.z *= inv; acc.w *= inv;

    *(uint2*)(wvp + (size_t)warp * 64 + colp) =
        make_uint2(pack2_f16(acc.x, acc.y), pack2_f16(acc.z, acc.w));
}

// ---------------------------------------------------------------------------
// Mean pool: per-block partial colsum from fp32 x (no atomics).
// ---------------------------------------------------------------------------
__global__ void colsum(const float* __restrict__ x, float* __restrict__ part, int N) {
    int d = threadIdx.x;
    float s = 0.0f;
    for (int r = blockIdx.x; r < N; r += gridDim.x)
        s += x[(size_t)r * D + d];
    part[(size_t)blockIdx.x * D + d] = s;
}

__global__ void readout(const float* __restrict__ part,
                        const float* __restrict__ mW0, const float* __restrict__ mb0,
                        const float* __restrict__ mW1, const float* __restrict__ mb1,
                        const float* __restrict__ mW2, const float* __restrict__ mb2,
                        float* __restrict__ out, int N) {
    __shared__ float m[D];
    __shared__ float h0[64];
    __shared__ float h1[32];
    int tid = threadIdx.x;
    float s0 = 0.f;
    for (int bqi = 0; bqi < NPARTBLK; bqi++) s0 += part[(size_t)bqi * D + tid];
    m[tid] = s0 * (1.0f / (float)N);
    __syncthreads();
    if (tid < 64) {
        float s = mb0[tid];
        for (int kk = 0; kk < D; kk++) s = fmaf(m[kk], mW0[kk * 64 + tid], s);
        h0[tid] = fmaxf(s, 0.0f);
    }
    __syncthreads();
    if (tid < 32) {
        float s = mb1[tid];
        for (int kk = 0; kk < 64; kk++) s = fmaf(h0[kk], mW1[kk * 32 + tid], s);
        h1[tid] = fmaxf(s, 0.0f);
    }
    __syncthreads();
    if (tid < 10) {
        float s = mb2[tid];
        for (int kk = 0; kk < 32; kk++) s = fmaf(h1[kk], mW2[kk * 10 + tid], s);
        out[tid] = s;
    }
}

// ---------------------------------------------------------------------------
extern "C" void kernel_launch(void* const* d_in, const int* in_sizes, int n_in,
                              void* d_out, int out_size) {
    const int*   x_idx = (const int*)d_in[0];
    const int*   ei    = (const int*)d_in[1];
    const float* emb   = (const float*)d_in[2];
    const float* Wq  = (const float*)d_in[3];
    const float* bq  = (const float*)d_in[4];
    const float* Wk  = (const float*)d_in[5];
    const float* bk  = (const float*)d_in[6];
    const float* Wv  = (const float*)d_in[7];
    const float* bv  = (const float*)d_in[8];
    const float* Wo  = (const float*)d_in[9];
    const float* bo  = (const float*)d_in[10];
    const float* g1  = (const float*)d_in[11];
    const float* be1 = (const float*)d_in[12];
    const float* Wf1 = (const float*)d_in[13];
    const float* bf1 = (const float*)d_in[14];
    const float* Wf2 = (const float*)d_in[15];
    const float* bf2 = (const float*)d_in[16];
    const float* g2  = (const float*)d_in[17];
    const float* be2 = (const float*)d_in[18];
    const float* mW0 = (const float*)d_in[19];
    const float* mb0 = (const float*)d_in[20];
    const float* mW1 = (const float*)d_in[21];
    const float* mb1 = (const float*)d_in[22];
    const float* mW2 = (const float*)d_in[23];
    const float* mb2 = (const float*)d_in[24];
    float* out = (float*)d_out;

    const int N = in_sizes[0];       // 50000
    const int E = in_sizes[1] / 2;   // 800000

    float* base;
    cudaGetSymbolAddress((void**)&base, g_scratch);
    float* x    = base + OFF_X;
    float* part = base + OFF_PART;

    int* ibase;
    cudaGetSymbolAddress((void**)&ibase, g_iscratch);
    int* cnt     = ibase + IOFF_CNT;
    int* rowptr  = ibase + IOFF_ROW;
    int* csr_src = ibase + IOFF_SRC;

    unsigned *wp, *xp, *yp, *qp, *kp, *vp, *wvp, *midp;
    cudaGetSymbolAddress((void**)&wp, g_wpack);
    cudaGetSymbolAddress((void**)&xp, g_xp);
    cudaGetSymbolAddress((void**)&yp, g_yp);
    cudaGetSymbolAddress((void**)&qp, g_qp);
    cudaGetSymbolAddress((void**)&kp, g_kp);
    cudaGetSymbolAddress((void**)&vp, g_vp);
    cudaGetSymbolAddress((void**)&wvp, g_wvp);
    cudaGetSymbolAddress((void**)&midp, g_midp);

    cudaFuncSetAttribute(gemm_qkv, cudaFuncAttributeMaxDynamicSharedMemorySize, GEMM_DYN_SMEM);
    cudaFuncSetAttribute(gemm_ln, cudaFuncAttributeMaxDynamicSharedMemorySize, GEMM_DYN_SMEM);
    cudaFuncSetAttribute(gemm_f1, cudaFuncAttributeMaxDynamicSharedMemorySize, GEMM_DYN_SMEM);

    const int nb64 = (N + 63) / 64;

    // --- Ordered so gemm_qkv is the 6th launch (ncu -s 5 -c 1 profiles it) ---
    conv_all<<<(WPACK_TOTAL + 255) / 256, 256>>>(Wq, Wk, Wv, Wo, Wf1, Wf2, wp); // 1
    emb_gather<<<(N * 64 + 255) / 256, 256>>>(x_idx, emb, x, xp, N);            // 2
    zero_int<<<(N + 255) / 256, 256>>>(cnt, N);                                 // 3
    hist_dst<<<(E + 255) / 256, 256>>>(ei, E, cnt);                             // 4
    scan_rowptr<<<1, 1024>>>(cnt, rowptr, N);   // also re-zeros cnt            // 5

    // Layer 0 QKV (6th launch -> profiled)
    gemm_qkv<<<dim3(nb64, 1, 3), 128, GEMM_DYN_SMEM>>>(
        xp, wp + WQ_OFF, wp + WK_OFF, wp + WV_OFF, bq, bk, bv, qp, kp, vp, N);

    // Finish CSR build (cnt already zeroed by scan_rowptr)
    csr_scatter<<<(E + 255) / 256, 256>>>(ei, E, rowptr, cnt, csr_src);

    for (int l = 0; l < LAYERS; l++) {
        const unsigned* wq_p = wp + WQ_OFF + (size_t)l * PQ;
        const unsigned* wk_p = wp + WK_OFF + (size_t)l * PQ;
        const unsigned* wv_p = wp + WV_OFF + (size_t)l * PQ;
        const unsigned* wo_p = wp + WO_OFF + (size_t)l * PQ;
        const unsigned* wf1_p = wp + WF1_OFF + (size_t)l * PF;
        const unsigned* wf2_p = wp + WF2_OFF + (size_t)l * PF;

        if (l > 0) {
            gemm_qkv<<<dim3(nb64, 1, 3), 128, GEMM_DYN_SMEM>>>(
                xp, wq_p, wk_p, wv_p, bq + l * D, bk + l * D, bv + l * D,
                qp, kp, vp, N);
        }

        attn_csr<<<(N + 7) / 8, 256>>>(rowptr, csr_src, qp, kp, vp, wvp, N);

        // y(packed) = wV@Wo + bo ; x = LN(x + y)   (fp32 residual)
        gemm_ln<<<nb64, 128, GEMM_DYN_SMEM>>>(
            wvp, 64, wo_p, 64, bo + l * D, yp, x, nullptr,
            g1 + l * D, be1 + l * D, N, 128);

        // mid(packed) = relu(y@Wf1 + bf1)
        gemm_f1<<<dim3(nb64, 2), 128, GEMM_DYN_SMEM>>>(yp, wf1_p, bf1 + l * 2 * D, midp, N);

        // x = LN(x + mid@Wf2 + bf2), also packed to xp
        gemm_ln<<<nb64, 128, GEMM_DYN_SMEM>>>(
            midp, 128, wf2_p, 128, bf2 + l * D, nullptr, x, xp,
            g2 + l * D, be2 + l * D, N, 256);
    }

    colsum<<<NPARTBLK, 128>>>(x, part, N);
    readout<<<1, 128>>>(part, mW0, mb0, mW1, mb1, mW2, mb2, out, N);
}

// round 16
// speedup vs baseline: 1.2165x; 1.2165x over previous
#include <cuda_runtime.h>
#include <cuda_fp16.h>
#include <cstddef>

#define D       128
#define H       8
#define HD      16
#define NMAX    50000
#define NPAD    50176          // 392 * 128
#define EMAX    800000
#define LAYERS  3

// ---------------------------------------------------------------------------
// Float scratch: x (residual/pool), colsum partials
// ---------------------------------------------------------------------------
#define OFF_X    ((size_t)0)
#define OFF_PART (OFF_X + (size_t)NMAX * D)
#define NPARTBLK 256
#define SCRATCH_FLOATS (OFF_PART + (size_t)NPARTBLK * D)
__device__ float g_scratch[SCRATCH_FLOATS];

// Packed fp16 activations (single plane, half2 per uint, pairs along K)
#define XPL   ((size_t)NPAD * 64)
#define MIDPL ((size_t)NPAD * 128)
__device__ unsigned g_xp[XPL];
__device__ unsigned g_yp[XPL];
__device__ unsigned g_qp[XPL];
__device__ unsigned g_kp[XPL];
__device__ unsigned g_vp[XPL];
__device__ unsigned g_wvp[XPL];
__device__ unsigned g_midp[MIDPL];

// Int scratch: cnt[N], rowptr[N+1], csr_src[E]
#define IOFF_CNT   0
#define IOFF_ROW   (IOFF_CNT + NMAX)
#define IOFF_SRC   (IOFF_ROW + NMAX + 1)
__device__ int g_iscratch[IOFF_SRC + EMAX];

// Packed fp16 weights, N-MAJOR rows of K-pairs: w[n][kp] (half2 per uint).
#define PQ      (64 * 128)     // DxD matrix (uints)
#define PF      (64 * 256)     // 128x256 / 256x128 (uints)
#define SQ      (LAYERS * PQ)
#define SF      (LAYERS * PF)
#define WQ_OFF  0
#define WK_OFF  (WQ_OFF + SQ)
#define WV_OFF  (WK_OFF + SQ)
#define WO_OFF  (WV_OFF + SQ)
#define WF1_OFF (WO_OFF + SQ)
#define WF2_OFF (WF1_OFF + SF)
#define WPACK_TOTAL (WF2_OFF + SF)
__device__ unsigned g_wpack[WPACK_TOTAL];

// ---------------------------------------------------------------------------
__device__ __forceinline__ unsigned pack2_f16(float a, float b) {
    __half2 h2 = __floats2half2_rn(a, b);
    return *(unsigned*)&h2;
}
__device__ __forceinline__ float2 unpack2_f16(unsigned u) {
    return __half22float2(*(__half2*)&u);
}
__device__ __forceinline__ void cp16(unsigned* smem, const unsigned* gmem) {
    unsigned sa = (unsigned)__cvta_generic_to_shared(smem);
    asm volatile("cp.async.cg.shared.global [%0], [%1], 16;" :: "r"(sa), "l"(gmem));
}
#define LDSM_X4(r0, r1, r2, r3, addr) \
    asm volatile("ldmatrix.sync.aligned.m8n8.x4.shared.b16 {%0,%1,%2,%3}, [%4];" \
                 : "=r"(r0), "=r"(r1), "=r"(r2), "=r"(r3) : "r"(addr))

// ---------------------------------------------------------------------------
__global__ void zero_int(int* __restrict__ p, int n) {
    int i = blockIdx.x * blockDim.x + threadIdx.x;
    int stride = gridDim.x * blockDim.x;
    for (; i < n; i += stride) p[i] = 0;
}

// Embedding gather: float x + packed xp
__global__ void emb_gather(const int* __restrict__ idx, const float* __restrict__ emb,
                           float* __restrict__ x, unsigned* __restrict__ xp, int N) {
    int i = blockIdx.x * blockDim.x + threadIdx.x;
    if (i >= N * 64) return;
    int n = i >> 6;
    int kp = i & 63;
    float2 e = *(const float2*)(emb + (size_t)idx[n] * D + 2 * kp);
    *(float2*)(x + (size_t)n * D + 2 * kp) = e;
    xp[(size_t)n * 64 + kp] = pack2_f16(e.x, e.y);
}

// Combined weight conversion: all 6 weight stacks in ONE launch.
// float [L, K, Nout] -> n-major packed: dst[l*P + n*(K/2) + kp]
__global__ void conv_all(const float* __restrict__ Wq, const float* __restrict__ Wk,
                         const float* __restrict__ Wv, const float* __restrict__ Wo,
                         const float* __restrict__ Wf1, const float* __restrict__ Wf2,
                         unsigned* __restrict__ wp) {
    int idx = blockIdx.x * blockDim.x + threadIdx.x;
    if (idx >= (int)WPACK_TOTAL) return;

    const float* src;
    int K, Nout, rem, dstoff;
    if (idx < 4 * SQ) {
        int which = idx / SQ;
        rem = idx - which * SQ;
        src = (which == 0) ? Wq : (which == 1) ? Wk : (which == 2) ? Wv : Wo;
        K = 128; Nout = 128;
        dstoff = which * SQ;
    } else if (idx < 4 * SQ + SF) {
        rem = idx - 4 * SQ;
        src = Wf1; K = 128; Nout = 256; dstoff = WF1_OFF;
    } else {
        rem = idx - 4 * SQ - SF;
        src = Wf2; K = 256; Nout = 128; dstoff = WF2_OFF;
    }
    int KH = K >> 1;
    int P = KH * Nout;
    int l = rem / P;
    int p = rem - l * P;
    int n = p / KH;
    int kp = p - n * KH;
    float a = src[(size_t)l * K * Nout + (size_t)(2 * kp) * Nout + n];
    float b = src[(size_t)l * K * Nout + (size_t)(2 * kp + 1) * Nout + n];
    wp[dstoff + (size_t)l * P + p] = pack2_f16(a, b);
}

// ---------------------------------------------------------------------------
// CSR build
// ---------------------------------------------------------------------------
__global__ void hist_dst(const int* __restrict__ ei, int E, int* __restrict__ cnt) {
    int j = blockIdx.x * blockDim.x + threadIdx.x;
    if (j < E) atomicAdd(&cnt[ei[E + j]], 1);
}
// Scan + re-zero cnt (cnt reused as 'cur' by csr_scatter, so no extra zero pass).
__global__ void scan_rowptr(int* __restrict__ cnt, int* __restrict__ rowptr, int N) {
    __shared__ int ssum[1024];
    int tid = threadIdx.x;
    int chunk = (N + 1023) / 1024;
    int start = tid * chunk;
    int end = min(start + chunk, N);
    int s = 0;
    for (int i = start; i < end; i++) s += cnt[i];
    ssum[tid] = s;
    __syncthreads();
    int mysum = s;
    for (int o = 1; o < 1024; o <<= 1) {
        int t = (tid >= o) ? ssum[tid - o] : 0;
        __syncthreads();
        ssum[tid] += t;
        __syncthreads();
    }
    int off = ssum[tid] - mysum;
    for (int i = start; i < end; i++) {
        rowptr[i] = off;
        off += cnt[i];
        cnt[i] = 0;
    }
    if (end == N) rowptr[N] = off;
}
__global__ void csr_scatter(const int* __restrict__ ei, int E,
                            const int* __restrict__ rowptr, int* __restrict__ cur,
                            int* __restrict__ csr_src) {
    int j = blockIdx.x * blockDim.x + threadIdx.x;
    if (j >= E) return;
    int d = ei[E + j];
    int pos = atomicAdd(&cur[d], 1);
    csr_src[rowptr[d] + pos] = ei[j];
}

// ---------------------------------------------------------------------------
// fp16 tensor-core GEMM core with ldmatrix fragment loads.
// Block tile 128x128, chunk K=32, 256 threads (8 warps: 4 M x 2 N, 32x64/warp).
// ---------------------------------------------------------------------------
#define ASTR 20
#define SM_A 0
#define SM_B 2560
#define STG_UINTS 5120
#define GEMM_DYN_SMEM (2 * STG_UINTS * 4)

__device__ __forceinline__ void mma_f16(float c[4], const unsigned a[4],
                                        unsigned b0, unsigned b1) {
    asm volatile(
        "mma.sync.aligned.m16n8k16.row.col.f32.f16.f16.f32 "
        "{%0,%1,%2,%3}, {%4,%5,%6,%7}, {%8,%9}, {%0,%1,%2,%3};"
        : "+f"(c[0]), "+f"(c[1]), "+f"(c[2]), "+f"(c[3])
        : "r"(a[0]), "r"(a[1]), "r"(a[2]), "r"(a[3]), "r"(b0), "r"(b1));
}

__device__ __forceinline__ void load_stage(
    const unsigned* __restrict__ Ap, int ldA,
    const unsigned* __restrict__ Wp, int ldW,
    int bm, int bn, int chunk, unsigned* s, int tid)
{
    int kp0 = chunk * 16;
#pragma unroll
    for (int it = 0; it < 2; it++) {
        int idx = tid + it * 256;
        int r = idx >> 2;
        int c4 = idx & 3;
        cp16(s + SM_A + r * ASTR + c4 * 4,
             Ap + (size_t)(bm + r) * ldA + kp0 + c4 * 4);
    }
#pragma unroll
    for (int it = 0; it < 2; it++) {
        int idx = tid + it * 256;
        int r = idx >> 2;
        int c4 = idx & 3;
        cp16(s + SM_B + r * ASTR + c4 * 4,
             Wp + (size_t)(bn + r) * ldW + kp0 + c4 * 4);
    }
    asm volatile("cp.async.commit_group;");
}

__device__ __forceinline__ void gemm_core_p(
    const unsigned* __restrict__ Ap, int ldA,
    const unsigned* __restrict__ Wp, int ldW,
    int K, int bm, int bn,
    unsigned* sm, float acc[2][8][4])
{
    const int tid = threadIdx.x;
    const int lane = tid & 31;
    const int wid = tid >> 5;
    const int warp_m = wid & 3;
    const int warp_n = wid >> 2;
    const int sub = lane >> 3;
    const int rin = lane & 7;

    const unsigned sbase = (unsigned)__cvta_generic_to_shared(sm);
    const int a_row = warp_m * 32 + (sub & 1) * 8 + rin;
    const int a_col = (sub >> 1) * 4;
    const int b_row0 = warp_n * 64 + (sub >> 1) * 8 + rin;
    const int b_col = (sub & 1) * 4;

#pragma unroll
    for (int mi = 0; mi < 2; mi++)
#pragma unroll
        for (int ni = 0; ni < 8; ni++)
#pragma unroll
            for (int t = 0; t < 4; t++) acc[mi][ni][t] = 0.0f;

    const int C = K >> 5;
    load_stage(Ap, ldA, Wp, ldW, bm, bn, 0, sm, tid);

    for (int c = 0; c < C; c++) {
        if (c + 1 < C) {
            load_stage(Ap, ldA, Wp, ldW, bm, bn, c + 1,
                       sm + ((c + 1) & 1) * STG_UINTS, tid);
            asm volatile("cp.async.wait_group 1;");
        } else {
            asm volatile("cp.async.wait_group 0;");
        }
        __syncthreads();

        const unsigned stg = sbase + (unsigned)((c & 1) * STG_UINTS) * 4u;

#pragma unroll
        for (int st = 0; st < 2; st++) {
            unsigned ah[2][4];
#pragma unroll
            for (int mi = 0; mi < 2; mi++) {
                unsigned aaddr = stg + ((unsigned)(SM_A + (a_row + mi * 16) * ASTR
                                                   + 8 * st + a_col) << 2);
                LDSM_X4(ah[mi][0], ah[mi][1], ah[mi][2], ah[mi][3], aaddr);
            }
#pragma unroll
            for (int t = 0; t < 4; t++) {
                unsigned b0, b1, b2, b3;
                unsigned baddr = stg + ((unsigned)(SM_B + (b_row0 + t * 16) * ASTR
                                                   + 8 * st + b_col) << 2);
                LDSM_X4(b0, b1, b2, b3, baddr);
#pragma unroll
                for (int mi = 0; mi < 2; mi++) {
                    mma_f16(acc[mi][2 * t + 0], ah[mi], b0, b1);
                    mma_f16(acc[mi][2 * t + 1], ah[mi], b2, b3);
                }
            }
        }
        __syncthreads();
    }
}

// QKV fused: grid.z selects weight/bias/output; packed half2 q/k/v outputs.
__global__ __launch_bounds__(256, 2)
void gemm_qkv(const unsigned* __restrict__ Ap,
              const unsigned* __restrict__ Wpq, const unsigned* __restrict__ Wpk,
              const unsigned* __restrict__ Wpv,
              const float* __restrict__ bq, const float* __restrict__ bk,
              const float* __restrict__ bv,
              unsigned* __restrict__ Cq, unsigned* __restrict__ Ck,
              unsigned* __restrict__ Cv,
              int rows) {
    extern __shared__ unsigned sm[];
    const int z = blockIdx.z;
    const unsigned* Wp = (z == 0) ? Wpq : (z == 1) ? Wpk : Wpv;
    const float* bias  = (z == 0) ? bq  : (z == 1) ? bk  : bv;
    unsigned* C        = (z == 0) ? Cq  : (z == 1) ? Ck  : Cv;
    const int bm = blockIdx.x * 128;
    float acc[2][8][4];
    gemm_core_p(Ap, 64, Wp, 64, 128, bm, 0, sm, acc);

    const int lane = threadIdx.x & 31;
    const int wid = threadIdx.x >> 5;
    const int warp_m = wid & 3, warp_n = wid >> 2;
    const int lr = lane >> 2, lc = lane & 3;
#pragma unroll
    for (int mi = 0; mi < 2; mi++) {
        int row0 = bm + warp_m * 32 + mi * 16 + lr;
        int row1 = row0 + 8;
#pragma unroll
        for (int ni = 0; ni < 8; ni++) {
            int col = warp_n * 64 + ni * 8 + 2 * lc;
            int colp = col >> 1;
            float bs0 = bias[col], bs1 = bias[col + 1];
            if (row0 < rows)
                C[(size_t)row0 * 64 + colp] =
                    pack2_f16(acc[mi][ni][0] + bs0, acc[mi][ni][1] + bs1);
            if (row1 < rows)
                C[(size_t)row1 * 64 + colp] =
                    pack2_f16(acc[mi][ni][2] + bs0, acc[mi][ni][3] + bs1);
        }
    }
}

// GEMM + fused residual/LayerNorm (Nout = 128 = full row per block).
// fp32 residual xio (load-bearing for accuracy), optional packed outputs.
__global__ __launch_bounds__(256, 2)
void gemm_ln(const unsigned* __restrict__ Ap, int ldA,
             const unsigned* __restrict__ Wp, int ldW,
             const float* __restrict__ bias,
             unsigned* __restrict__ yp,
             float* __restrict__ xio,
             unsigned* __restrict__ xpo,
             const float* __restrict__ g, const float* __restrict__ b,
             int rows, int K) {
    extern __shared__ unsigned sm[];
    const int bm = blockIdx.x * 128;
    float acc[2][8][4];
    gemm_core_p(Ap, ldA, Wp, ldW, K, bm, 0, sm, acc);

    const int lane = threadIdx.x & 31;
    const int wid = threadIdx.x >> 5;
    const int warp_m = wid & 3, warp_n = wid >> 2;
    const int lr = lane >> 2, lc = lane & 3;

    float* sred = (float*)sm;

#pragma unroll
    for (int mi = 0; mi < 2; mi++) {
#pragma unroll
        for (int rp = 0; rp < 2; rp++) {
            int r_loc = warp_m * 32 + mi * 16 + lr + 8 * rp;
            int row = bm + r_loc;
            float sum = 0.f, sq = 0.f;
#pragma unroll
            for (int ni = 0; ni < 8; ni++) {
                int col = warp_n * 64 + ni * 8 + 2 * lc;
                float o0 = acc[mi][ni][2 * rp + 0] + bias[col];
                float o1 = acc[mi][ni][2 * rp + 1] + bias[col + 1];
                float x0 = 0.f, x1 = 0.f;
                if (row < rows) {
                    float2 xr = *(const float2*)(xio + (size_t)row * D + col);
                    x0 = xr.x; x1 = xr.y;
                    if (yp)
                        yp[(size_t)row * 64 + (col >> 1)] = pack2_f16(o0, o1);
                }
                float v0 = o0 + x0, v1 = o1 + x1;
                acc[mi][ni][2 * rp + 0] = v0;
                acc[mi][ni][2 * rp + 1] = v1;
                sum += v0 + v1;
                sq += v0 * v0 + v1 * v1;
            }
            sum += __shfl_xor_sync(0xffffffffu, sum, 1);
            sq  += __shfl_xor_sync(0xffffffffu, sq, 1);
            sum += __shfl_xor_sync(0xffffffffu, sum, 2);
            sq  += __shfl_xor_sync(0xffffffffu, sq, 2);
            if (lc == 0) {
                sred[r_loc * 4 + warp_n * 2 + 0] = sum;
                sred[r_loc * 4 + warp_n * 2 + 1] = sq;
            }
        }
    }
    __syncthreads();

#pragma unroll
    for (int mi = 0; mi < 2; mi++) {
#pragma unroll
        for (int rp = 0; rp < 2; rp++) {
            int r_loc = warp_m * 32 + mi * 16 + lr + 8 * rp;
            int row = bm + r_loc;
            if (row >= rows) continue;
            float sum = sred[r_loc * 4 + 0] + sred[r_loc * 4 + 2];
            float sq  = sred[r_loc * 4 + 1] + sred[r_loc * 4 + 3];
            float mean = sum * (1.0f / 128.0f);
            float var = sq * (1.0f / 128.0f) - mean * mean;
            float rstd = rsqrtf(var + 1e-5f);
#pragma unroll
            for (int ni = 0; ni < 8; ni++) {
                int col = warp_n * 64 + ni * 8 + 2 * lc;
                float v0 = acc[mi][ni][2 * rp + 0];
                float v1 = acc[mi][ni][2 * rp + 1];
                float out0 = (v0 - mean) * rstd * g[col] + b[col];
                float out1 = (v1 - mean) * rstd * g[col + 1] + b[col + 1];
                *(float2*)(xio + (size_t)row * D + col) = make_float2(out0, out1);
                if (xpo)
                    xpo[(size_t)row * 64 + (col >> 1)] = pack2_f16(out0, out1);
            }
        }
    }
}

// FFN first GEMM: relu, packed output (Nout = 256 via grid.y)
__global__ __launch_bounds__(256, 2)
void gemm_f1(const unsigned* __restrict__ Ap,
             const unsigned* __restrict__ Wp,
             const float* __restrict__ bias,
             unsigned* __restrict__ outp,
             int rows) {
    extern __shared__ unsigned sm[];
    const int bm = blockIdx.x * 128;
    const int bn = blockIdx.y * 128;
    float acc[2][8][4];
    gemm_core_p(Ap, 64, Wp, 64, 128, bm, bn, sm, acc);

    const int lane = threadIdx.x & 31;
    const int wid = threadIdx.x >> 5;
    const int warp_m = wid & 3, warp_n = wid >> 2;
    const int lr = lane >> 2, lc = lane & 3;
#pragma unroll
    for (int mi = 0; mi < 2; mi++) {
        int row0 = bm + warp_m * 32 + mi * 16 + lr;
        int row1 = row0 + 8;
#pragma unroll
        for (int ni = 0; ni < 8; ni++) {
            int col = bn + warp_n * 64 + ni * 8 + 2 * lc;
            int colp = col >> 1;
            float bs0 = bias[col], bs1 = bias[col + 1];
            float o0 = fmaxf(acc[mi][ni][0] + bs0, 0.f);
            float o1 = fmaxf(acc[mi][ni][1] + bs1, 0.f);
            float o2 = fmaxf(acc[mi][ni][2] + bs0, 0.f);
            float o3 = fmaxf(acc[mi][ni][3] + bs1, 0.f);
            if (row0 < rows)
                outp[(size_t)row0 * 128 + colp] = pack2_f16(o0, o1);
            if (row1 < rows)
                outp[(size_t)row1 * 128 + colp] = pack2_f16(o2, o3);
        }
    }
}

// ---------------------------------------------------------------------------
// CSR attention: warp per destination node, fp16 q/k/v, 2-edge unrolled.
// ---------------------------------------------------------------------------
__global__ void attn_csr(const int* __restrict__ rowptr, const int* __restrict__ csr_src,
                         const unsigned* __restrict__ qh, const unsigned* __restrict__ kh,
                         const unsigned* __restrict__ vh, unsigned* __restrict__ wvp, int N) {
    int warp = blockIdx.x * (blockDim.x >> 5) + (threadIdx.x >> 5);
    if (warp >= N) return;
    int lane = threadIdx.x & 31;
    int colp = lane * 2;

    uint2 qp = *(const uint2*)(qh + (size_t)warp * 64 + colp);
    float2 q01 = unpack2_f16(qp.x);
    float2 q23 = unpack2_f16(qp.y);

    float4 acc = make_float4(0.f, 0.f, 0.f, 0.f);
    float Zh = 0.0f;

    int jb = rowptr[warp];
    int je = rowptr[warp + 1];
    int j = jb;

    for (; j + 1 < je; j += 2) {
        int s0 = csr_src[j];
        int s1 = csr_src[j + 1];
        uint2 ka = *(const uint2*)(kh + (size_t)s0 * 64 + colp);
        uint2 kb = *(const uint2*)(kh + (size_t)s1 * 64 + colp);
        uint2 va = *(const uint2*)(vh + (size_t)s0 * 64 + colp);
        uint2 vb = *(const uint2*)(vh + (size_t)s1 * 64 + colp);

        float2 ka01 = unpack2_f16(ka.x), ka23 = unpack2_f16(ka.y);
        float2 kb01 = unpack2_f16(kb.x), kb23 = unpack2_f16(kb.y);
        float sa = ka01.x * q01.x + ka01.y * q01.y + ka23.x * q23.x + ka23.y * q23.y;
        float sb = kb01.x * q01.x + kb01.y * q01.y + kb23.x * q23.x + kb23.y * q23.y;
        sa += __shfl_xor_sync(0xffffffffu, sa, 1);
        sb += __shfl_xor_sync(0xffffffffu, sb, 1);
        sa += __shfl_xor_sync(0xffffffffu, sa, 2);
        sb += __shfl_xor_sync(0xffffffffu, sb, 2);
        sa = expf(fminf(fmaxf(sa * 0.25f, -5.0f), 5.0f));
        sb = expf(fminf(fmaxf(sb * 0.25f, -5.0f), 5.0f));

        float2 va01 = unpack2_f16(va.x), va23 = unpack2_f16(va.y);
        float2 vb01 = unpack2_f16(vb.x), vb23 = unpack2_f16(vb.y);
        acc.x = fmaf(va01.x, sa, fmaf(vb01.x, sb, acc.x));
        acc.y = fmaf(va01.y, sa, fmaf(vb01.y, sb, acc.y));
        acc.z = fmaf(va23.x, sa, fmaf(vb23.x, sb, acc.z));
        acc.w = fmaf(va23.y, sa, fmaf(vb23.y, sb, acc.w));
        Zh += sa + sb;
    }
    if (j < je) {
        int s0 = csr_src[j];
        uint2 ka = *(const uint2*)(kh + (size_t)s0 * 64 + colp);
        uint2 va = *(const uint2*)(vh + (size_t)s0 * 64 + colp);
        float2 k01 = unpack2_f16(ka.x), k23 = unpack2_f16(ka.y);
        float s = k01.x * q01.x + k01.y * q01.y + k23.x * q23.x + k23.y * q23.y;
        s += __shfl_xor_sync(0xffffffffu, s, 1);
        s += __shfl_xor_sync(0xffffffffu, s, 2);
        s = expf(fminf(fmaxf(s * 0.25f, -5.0f), 5.0f));
        float2 v01 = unpack2_f16(va.x), v23 = unpack2_f16(va.y);
        acc.x = fmaf(v01.x, s, acc.x);
        acc.y = fmaf(v01.y, s, acc.y);
        acc.z = fmaf(v23.x, s, acc.z);
        acc.w = fmaf(v23.y, s, acc.w);
        Zh += s;
    }
    float inv = 1.0f / (Zh + 1e-6f);
    acc.x *= inv; acc.y *= inv; acc.z *= inv; acc.w *= inv;

    *(uint2*)(wvp + (size_t)warp * 64 + colp) =
        make_uint2(pack2_f16(acc.x, acc.y), pack2_f16(acc.z, acc.w));
}

// ---------------------------------------------------------------------------
// Mean pool: per-block partial colsum from fp32 x (no atomics).
// ---------------------------------------------------------------------------
__global__ void colsum(const float* __restrict__ x, float* __restrict__ part, int N) {
    int d = threadIdx.x;
    float s = 0.0f;
    for (int r = blockIdx.x; r < N; r += gridDim.x)
        s += x[(size_t)r * D + d];
    part[(size_t)blockIdx.x * D + d] = s;
}

__global__ void readout(const float* __restrict__ part,
                        const float* __restrict__ mW0, const float* __restrict__ mb0,
                        const float* __restrict__ mW1, const float* __restrict__ mb1,
                        const float* __restrict__ mW2, const float* __restrict__ mb2,
                        float* __restrict__ out, int N) {
    __shared__ float m[D];
    __shared__ float h0[64];
    __shared__ float h1[32];
    int tid = threadIdx.x;
    float s0 = 0.f;
    for (int bqi = 0; bqi < NPARTBLK; bqi++) s0 += part[(size_t)bqi * D + tid];
    m[tid] = s0 * (1.0f / (float)N);
    __syncthreads();
    if (tid < 64) {
        float s = mb0[tid];
        for (int kk = 0; kk < D; kk++) s = fmaf(m[kk], mW0[kk * 64 + tid], s);
        h0[tid] = fmaxf(s, 0.0f);
    }
    __syncthreads();
    if (tid < 32) {
        float s = mb1[tid];
        for (int kk = 0; kk < 64; kk++) s = fmaf(h0[kk], mW1[kk * 32 + tid], s);
        h1[tid] = fmaxf(s, 0.0f);
    }
    __syncthreads();
    if (tid < 10) {
        float s = mb2[tid];
        for (int kk = 0; kk < 32; kk++) s = fmaf(h1[kk], mW2[kk * 10 + tid], s);
        out[tid] = s;
    }
}

// ---------------------------------------------------------------------------
extern "C" void kernel_launch(void* const* d_in, const int* in_sizes, int n_in,
                              void* d_out, int out_size) {
    const int*   x_idx = (const int*)d_in[0];
    const int*   ei    = (const int*)d_in[1];
    const float* emb   = (const float*)d_in[2];
    const float* Wq  = (const float*)d_in[3];
    const float* bq  = (const float*)d_in[4];
    const float* Wk  = (const float*)d_in[5];
    const float* bk  = (const float*)d_in[6];
    const float* Wv  = (const float*)d_in[7];
    const float* bv  = (const float*)d_in[8];
    const float* Wo  = (const float*)d_in[9];
    const float* bo  = (const float*)d_in[10];
    const float* g1  = (const float*)d_in[11];
    const float* be1 = (const float*)d_in[12];
    const float* Wf1 = (const float*)d_in[13];
    const float* bf1 = (const float*)d_in[14];
    const float* Wf2 = (const float*)d_in[15];
    const float* bf2 = (const float*)d_in[16];
    const float* g2  = (const float*)d_in[17];
    const float* be2 = (const float*)d_in[18];
    const float* mW0 = (const float*)d_in[19];
    const float* mb0 = (const float*)d_in[20];
    const float* mW1 = (const float*)d_in[21];
    const float* mb1 = (const float*)d_in[22];
    const float* mW2 = (const float*)d_in[23];
    const float* mb2 = (const float*)d_in[24];
    float* out = (float*)d_out;

    const int N = in_sizes[0];       // 50000
    const int E = in_sizes[1] / 2;   // 800000

    float* base;
    cudaGetSymbolAddress((void**)&base, g_scratch);
    float* x    = base + OFF_X;
    float* part = base + OFF_PART;

    int* ibase;
    cudaGetSymbolAddress((void**)&ibase, g_iscratch);
    int* cnt     = ibase + IOFF_CNT;
    int* rowptr  = ibase + IOFF_ROW;
    int* csr_src = ibase + IOFF_SRC;

    unsigned *wp, *xp, *yp, *qp, *kp, *vp, *wvp, *midp;
    cudaGetSymbolAddress((void**)&wp, g_wpack);
    cudaGetSymbolAddress((void**)&xp, g_xp);
    cudaGetSymbolAddress((void**)&yp, g_yp);
    cudaGetSymbolAddress((void**)&qp, g_qp);
    cudaGetSymbolAddress((void**)&kp, g_kp);
    cudaGetSymbolAddress((void**)&vp, g_vp);
    cudaGetSymbolAddress((void**)&wvp, g_wvp);
    cudaGetSymbolAddress((void**)&midp, g_midp);

    cudaFuncSetAttribute(gemm_qkv, cudaFuncAttributeMaxDynamicSharedMemorySize, GEMM_DYN_SMEM);
    cudaFuncSetAttribute(gemm_ln, cudaFuncAttributeMaxDynamicSharedMemorySize, GEMM_DYN_SMEM);
    cudaFuncSetAttribute(gemm_f1, cudaFuncAttributeMaxDynamicSharedMemorySize, GEMM_DYN_SMEM);

    const int nb128 = (N + 127) / 128;

    // --- Ordered so gemm_qkv is the 6th launch (ncu -s 5 -c 1 profiles it) ---
    conv_all<<<(WPACK_TOTAL + 255) / 256, 256>>>(Wq, Wk, Wv, Wo, Wf1, Wf2, wp); // 1
    emb_gather<<<(N * 64 + 255) / 256, 256>>>(x_idx, emb, x, xp, N);            // 2
    zero_int<<<(N + 255) / 256, 256>>>(cnt, N);                                 // 3
    hist_dst<<<(E + 255) / 256, 256>>>(ei, E, cnt);                             // 4
    scan_rowptr<<<1, 1024>>>(cnt, rowptr, N);   // also re-zeros cnt            // 5

    // Layer 0 QKV (6th launch -> profiled)
    gemm_qkv<<<dim3(nb128, 1, 3), 256, GEMM_DYN_SMEM>>>(
        xp, wp + WQ_OFF, wp + WK_OFF, wp + WV_OFF, bq, bk, bv, qp, kp, vp, N);

    // Finish CSR build (cnt already zeroed by scan_rowptr)
    csr_scatter<<<(E + 255) / 256, 256>>>(ei, E, rowptr, cnt, csr_src);

    for (int l = 0; l < LAYERS; l++) {
        const unsigned* wq_p = wp + WQ_OFF + (size_t)l * PQ;
        const unsigned* wk_p = wp + WK_OFF + (size_t)l * PQ;
        const unsigned* wv_p = wp + WV_OFF + (size_t)l * PQ;
        const unsigned* wo_p = wp + WO_OFF + (size_t)l * PQ;
        const unsigned* wf1_p = wp + WF1_OFF + (size_t)l * PF;
        const unsigned* wf2_p = wp + WF2_OFF + (size_t)l * PF;

        if (l > 0) {
            gemm_qkv<<<dim3(nb128, 1, 3), 256, GEMM_DYN_SMEM>>>(
                xp, wq_p, wk_p, wv_p, bq + l * D, bk + l * D, bv + l * D,
                qp, kp, vp, N);
        }

        attn_csr<<<(N + 7) / 8, 256>>>(rowptr, csr_src, qp, kp, vp, wvp, N);

        // y(packed) = wV@Wo + bo ; x = LN(x + y)   (fp32 residual)
        gemm_ln<<<nb128, 256, GEMM_DYN_SMEM>>>(
            wvp, 64, wo_p, 64, bo + l * D, yp, x, nullptr,
            g1 + l * D, be1 + l * D, N, 128);

        // mid(packed) = relu(y@Wf1 + bf1)
        gemm_f1<<<dim3(nb128, 2), 256, GEMM_DYN_SMEM>>>(yp, wf1_p, bf1 + l * 2 * D, midp, N);

        // x = LN(x + mid@Wf2 + bf2), also packed to xp
        gemm_ln<<<nb128, 256, GEMM_DYN_SMEM>>>(
            midp, 128, wf2_p, 128, bf2 + l * D, nullptr, x, xp,
            g2 + l * D, be2 + l * D, N, 256);
    }

    colsum<<<NPARTBLK, 128>>>(x, part, N);
    readout<<<1, 128>>>(part, mW0, mb0, mW1, mb1, mW2, mb2, out, N);
}